// round 16
// baseline (speedup 1.0000x reference)
#include <cuda_runtime.h>
#include <math.h>
#include <stdint.h>

// ---------------------------------------------------------------------------
// HE_ColorNormalization, SMEM-resident persistent NMF, lean-tail iteration.
//   d_in[0] pic float32 (3,1024,1024) | d_in[1] W_target (3,4) | d_in[2] Ht_RM ()
//   d_in[3] W0 (N,4) | d_in[4] H0 (3,4)    Output: float32 (3,1024,1024)
// 148 CTAs x 768 thr; Wc + V in smem. f32x2 sweep. Per iteration: 3 syncs,
// no nanosleep, no serial Hd step (every thread computes Hd redundantly).
// ---------------------------------------------------------------------------

#define N_PIX    1048576
#define N_ITERS  100
#define EPSF     1e-8f
#define GRID     148
#define NTHR     768
#define NWARP    (NTHR / 32)
#define PPC      7086                    // pixels owned per CTA
#define KMAX     10
#define PPC_PAD  (KMAX * NTHR)           // 7680, zero-padded tail
#define TOTAL    (4 * N_PIX)
#define RANK0    4152359u                // floor(0.99*(TOTAL-1))
#define RANK1    4152360u
#define HREP     16
#define SMEM_BYTES (PPC_PAD * 28)        // 215040 bytes

typedef unsigned long long u64;

__device__ __forceinline__ u64 pk2(float lo, float hi) {
    u64 r; asm("mov.b64 %0, {%1, %2};" : "=l"(r) : "f"(lo), "f"(hi)); return r;
}
__device__ __forceinline__ void upk2(u64 v, float& lo, float& hi) {
    asm("mov.b64 {%0, %1}, %2;" : "=f"(lo), "=f"(hi) : "l"(v));
}
__device__ __forceinline__ u64 fma2_(u64 a, u64 b, u64 c) {
    u64 d; asm("fma.rn.f32x2 %0, %1, %2, %3;" : "=l"(d) : "l"(a), "l"(b), "l"(c)); return d;
}
__device__ __forceinline__ u64 mul2_(u64 a, u64 b) {
    u64 d; asm("mul.rn.f32x2 %0, %1, %2;" : "=l"(d) : "l"(a), "l"(b)); return d;
}

// Scratch (static device globals: no allocation allowed)
__device__ float4   g_Wc[N_PIX];
__device__ float    g_part[2][22][GRID];
__device__ unsigned g_arrive;
__device__ unsigned g_hist1[HREP * 65536];
__device__ unsigned g_hsum[65536];
__device__ unsigned g_hist2a[65536];
__device__ unsigned g_hist2b[65536];
__device__ unsigned g_bA, g_bB, g_cumA, g_cumB;
__device__ float    g_scale;

__device__ __forceinline__ float od_clip(float x) {
    x = fminf(fmaxf(x, 0.01f), 0.99f);
    return -__logf(x);
}

// --------------------------------------------------------------------------
__global__ void k_init_a() {
    int i = blockIdx.x * blockDim.x + threadIdx.x;
    int stride = gridDim.x * blockDim.x;
    uint4 z = make_uint4(0u, 0u, 0u, 0u);
    uint4* h1 = (uint4*)g_hist1;
    for (int h = i; h < HREP * 65536 / 4; h += stride) h1[h] = z;
}
__global__ void k_init_b() {
    int i = blockIdx.x * blockDim.x + threadIdx.x;
    int stride = gridDim.x * blockDim.x;
    uint4 z = make_uint4(0u, 0u, 0u, 0u);
    uint4* h2a = (uint4*)g_hist2a;
    uint4* h2b = (uint4*)g_hist2b;
    for (int h = i; h < 65536 / 4; h += stride) { h2a[h] = z; h2b[h] = z; }
}
__global__ void k_init_c() {
    if (threadIdx.x == 0 && blockIdx.x == 0) g_arrive = 0u;
}

// --------------------------------------------------------------------------
__global__ __launch_bounds__(NTHR, 1) void k_loop(const float* __restrict__ pic,
                                                  const float* __restrict__ W0,
                                                  const float* __restrict__ H0) {
    extern __shared__ float smem_dyn[];
    float4* swc = (float4*)smem_dyn;            // [PPC_PAD]
    float*  sv0 = (float*)(swc + PPC_PAD);      // [PPC_PAD]
    float*  sv1 = sv0 + PPC_PAD;
    float*  sv2 = sv1 + PPC_PAD;

    __shared__ float red[NWARP][22];
    __shared__ float tot[22];

    const int tid  = threadIdx.x;
    const int cta  = blockIdx.x;
    const int warp = tid >> 5, lane = tid & 31;
    const int base = cta * PPC;

    // Hd in registers, identical in every thread (uniform LDG broadcast)
    float hd[12];
#pragma unroll
    for (int t = 0; t < 12; t++) hd[t] = __ldg(&H0[t]);

    // Prologue: load slab (zero the pad so it contributes nothing)
    const float4* w04 = (const float4*)W0;
    for (int l = tid; l < PPC_PAD; l += NTHR) {
        int p = base + l;
        bool ok = (l < PPC) && (p < N_PIX);
        if (ok) {
            swc[l] = w04[p];
            sv0[l] = od_clip(pic[p]);
            sv1[l] = od_clip(pic[N_PIX + p]);
            sv2[l] = od_clip(pic[2 * N_PIX + p]);
        } else {
            swc[l] = make_float4(0.f, 0.f, 0.f, 0.f);
            sv0[l] = 0.f; sv1[l] = 0.f; sv2[l] = 0.f;
        }
    }
    __syncthreads();

    unsigned* hist = &g_hist1[(cta & (HREP - 1)) * 65536];

    for (int iter = 0; iter < N_ITERS; iter++) {
        // pack Hd + Gram; hd[] is dead during the sweep (carried by hd2)
        u64 hd2[3][2], G2[4][2];
#pragma unroll
        for (int c = 0; c < 3; c++) {
            hd2[c][0] = pk2(hd[c*4+0], hd[c*4+1]);
            hd2[c][1] = pk2(hd[c*4+2], hd[c*4+3]);
        }
#pragma unroll
        for (int k = 0; k < 4; k++) {
            float gk0 = hd[k]*hd[0] + hd[4+k]*hd[4+0] + hd[8+k]*hd[8+0];
            float gk1 = hd[k]*hd[1] + hd[4+k]*hd[4+1] + hd[8+k]*hd[8+1];
            float gk2 = hd[k]*hd[2] + hd[4+k]*hd[4+2] + hd[8+k]*hd[8+2];
            float gk3 = hd[k]*hd[3] + hd[4+k]*hd[4+3] + hd[8+k]*hd[8+3];
            G2[k][0] = pk2(gk0, gk1);
            G2[k][1] = pk2(gk2, gk3);
        }
        const u64 eps2 = pk2(EPSF, EPSF);

        u64 aA[3][2];
        float aB[10];
#pragma unroll
        for (int c = 0; c < 3; c++) { aA[c][0] = 0ull; aA[c][1] = 0ull; }
#pragma unroll
        for (int t = 0; t < 10; t++) aB[t] = 0.0f;

        const bool last = (iter == N_ITERS - 1);

#pragma unroll
        for (int k = 0; k < KMAX; k++) {
            const int l = tid + k * NTHR;

            float4 w = swc[l];
            float v0 = sv0[l], v1 = sv1[l], v2 = sv2[l];

            u64 vb0 = pk2(v0, v0), vb1 = pk2(v1, v1), vb2 = pk2(v2, v2);
            u64 n0 = fma2_(vb0, hd2[0][0], fma2_(vb1, hd2[1][0], mul2_(vb2, hd2[2][0])));
            u64 n1 = fma2_(vb0, hd2[0][1], fma2_(vb1, hd2[1][1], mul2_(vb2, hd2[2][1])));

            u64 wb0 = pk2(w.x, w.x), wb1 = pk2(w.y, w.y);
            u64 wb2 = pk2(w.z, w.z), wb3 = pk2(w.w, w.w);
            u64 d0 = fma2_(wb0, G2[0][0], fma2_(wb1, G2[1][0],
                     fma2_(wb2, G2[2][0], fma2_(wb3, G2[3][0], eps2))));
            u64 d1 = fma2_(wb0, G2[0][1], fma2_(wb1, G2[1][1],
                     fma2_(wb2, G2[2][1], fma2_(wb3, G2[3][1], eps2))));

            float num0, num1, num2, num3, den0, den1, den2, den3;
            upk2(n0, num0, num1); upk2(n1, num2, num3);
            upk2(d0, den0, den1); upk2(d1, den2, den3);

            float nw0 = w.x * __fdividef(num0, den0);
            float nw1 = w.y * __fdividef(num1, den1);
            float nw2 = w.z * __fdividef(num2, den2);
            float nw3 = w.w * __fdividef(num3, den3);
            swc[l] = make_float4(nw0, nw1, nw2, nw3);

            // A = V @ nw  (packed, 6 fma2)
            u64 nwp0 = pk2(nw0, nw1), nwp1 = pk2(nw2, nw3);
            aA[0][0] = fma2_(vb0, nwp0, aA[0][0]); aA[0][1] = fma2_(vb0, nwp1, aA[0][1]);
            aA[1][0] = fma2_(vb1, nwp0, aA[1][0]); aA[1][1] = fma2_(vb1, nwp1, aA[1][1]);
            aA[2][0] = fma2_(vb2, nwp0, aA[2][0]); aA[2][1] = fma2_(vb2, nwp1, aA[2][1]);

            // B = nw (x) nw, symmetric 10 (scalar)
            aB[0] += nw0*nw0; aB[1] += nw0*nw1; aB[2] += nw0*nw2; aB[3] += nw0*nw3;
            aB[4] += nw1*nw1; aB[5] += nw1*nw2; aB[6] += nw1*nw3;
            aB[7] += nw2*nw2; aB[8] += nw2*nw3; aB[9] += nw3*nw3;

            if (last) {
                int p = base + l;
                if (l < PPC && p < N_PIX) {
                    g_Wc[p] = make_float4(nw0, nw1, nw2, nw3);
                    atomicAdd(&hist[__float_as_uint(nw0) >> 16], 1u);
                    atomicAdd(&hist[__float_as_uint(nw1) >> 16], 1u);
                    atomicAdd(&hist[__float_as_uint(nw2) >> 16], 1u);
                    atomicAdd(&hist[__float_as_uint(nw3) >> 16], 1u);
                }
            }
        }

        if (last) break;

        float acc[22];
        upk2(aA[0][0], acc[0],  acc[1]);  upk2(aA[0][1], acc[2],  acc[3]);
        upk2(aA[1][0], acc[4],  acc[5]);  upk2(aA[1][1], acc[6],  acc[7]);
        upk2(aA[2][0], acc[8],  acc[9]);  upk2(aA[2][1], acc[10], acc[11]);
#pragma unroll
        for (int t = 0; t < 10; t++) acc[12 + t] = aB[t];

        // warp-level reduction
#pragma unroll
        for (int t = 0; t < 22; t++)
#pragma unroll
            for (int off = 16; off > 0; off >>= 1)
                acc[t] += __shfl_down_sync(0xFFFFFFFFu, acc[t], off);
        if (lane == 0) {
#pragma unroll
            for (int t = 0; t < 22; t++) red[warp][t] = acc[t];
        }
        __syncthreads();                                   // sync 1

        // warp 0: cross-warp sum, publish partials, global barrier
        if (warp == 0) {
            if (lane < 22) {
                float s = 0.0f;
#pragma unroll
                for (int w = 0; w < NWARP; w++) s += red[w][lane];
                g_part[iter & 1][lane][cta] = s;
                __threadfence();
            }
            __syncwarp();
            if (lane == 0) {
                atomicAdd(&g_arrive, 1u);
                const unsigned target = (unsigned)(iter + 1) * (unsigned)GRID;
                const volatile unsigned* va = &g_arrive;
                while (*va < target) { }                   // tight spin, no sleep
                __threadfence();
            }
            __syncwarp();
        }
        __syncthreads();                                   // sync 2

        // warps 0..21: reduce the 148 partials for one value each (fixed order)
        if (warp < 22) {
            float s = 0.0f;
            for (int b = lane; b < GRID; b += 32)
                s += __ldcg(&g_part[iter & 1][warp][b]);
#pragma unroll
            for (int off = 16; off > 0; off >>= 1)
                s += __shfl_down_sync(0xFFFFFFFFu, s, off);
            if (lane == 0) tot[warp] = s;
        }
        __syncthreads();                                   // sync 3

        // redundant per-thread Hd update (old Hd unpacked from live hd2 pairs;
        // all indices compile-time constant -> stays in registers)
        {
            float oh[12];
            upk2(hd2[0][0], oh[0], oh[1]);  upk2(hd2[0][1], oh[2],  oh[3]);
            upk2(hd2[1][0], oh[4], oh[5]);  upk2(hd2[1][1], oh[6],  oh[7]);
            upk2(hd2[2][0], oh[8], oh[9]);  upk2(hd2[2][1], oh[10], oh[11]);
#pragma unroll
            for (int c = 0; c < 3; c++)
#pragma unroll
                for (int j = 0; j < 4; j++) {
                    float den = EPSF;
#pragma unroll
                    for (int k = 0; k < 4; k++) {
                        int a = k < j ? k : j;
                        int b = k < j ? j : k;
                        int idx = a * 4 - ((a * (a + 1)) >> 1) + b;  // sym(4)
                        den += oh[c * 4 + k] * tot[12 + idx];
                    }
                    hd[c * 4 + j] = oh[c * 4 + j] * __fdividef(tot[c * 4 + j], den);
                }
        }
    }
}

// ---------------------------------------------------------------------------
// Pre-sum the HREP histogram replicas (full grid) so k_sel1 reads 256KB once.
__global__ void k_hsum() {
    int bin = blockIdx.x * blockDim.x + threadIdx.x;
    if (bin < 65536) {
        unsigned s = 0;
#pragma unroll
        for (int r = 0; r < HREP; r++) s += g_hist1[r * 65536 + bin];
        g_hsum[bin] = s;
    }
}

__global__ void k_sel1() {
    __shared__ unsigned chunk[1024];
    int tid = threadIdx.x;
    unsigned s = 0;
    for (int k = 0; k < 64; k++) s += g_hsum[tid * 64 + k];
    chunk[tid] = s;
    __syncthreads();
    if (tid == 0) {
        unsigned run = 0;
        for (int i = 0; i < 1024; i++) { unsigned c = chunk[i]; chunk[i] = run; run += c; }
    }
    __syncthreads();
    unsigned c = chunk[tid];
    for (int k = 0; k < 64; k++) {
        unsigned bin = tid * 64 + k;
        unsigned h = g_hsum[bin];
        if (RANK0 >= c && RANK0 < c + h) { g_bA = bin; g_cumA = c; }
        if (RANK1 >= c && RANK1 < c + h) { g_bB = bin; g_cumB = c; }
        c += h;
    }
}

__global__ void k_hist2() {
    unsigned bA = g_bA, bB = g_bB;
    const uint4* p = (const uint4*)g_Wc;
    int i = blockIdx.x * blockDim.x + threadIdx.x;
    int stride = gridDim.x * blockDim.x;
    for (; i < N_PIX; i += stride) {
        uint4 u = p[i];
        unsigned h0 = u.x >> 16, h1 = u.y >> 16, h2 = u.z >> 16, h3 = u.w >> 16;
        if (h0 == bA) atomicAdd(&g_hist2a[u.x & 0xFFFFu], 1u);
        if (h0 == bB) atomicAdd(&g_hist2b[u.x & 0xFFFFu], 1u);
        if (h1 == bA) atomicAdd(&g_hist2a[u.y & 0xFFFFu], 1u);
        if (h1 == bB) atomicAdd(&g_hist2b[u.y & 0xFFFFu], 1u);
        if (h2 == bA) atomicAdd(&g_hist2a[u.z & 0xFFFFu], 1u);
        if (h2 == bB) atomicAdd(&g_hist2b[u.z & 0xFFFFu], 1u);
        if (h3 == bA) atomicAdd(&g_hist2a[u.w & 0xFFFFu], 1u);
        if (h3 == bB) atomicAdd(&g_hist2b[u.w & 0xFFFFu], 1u);
    }
}

__device__ __forceinline__ void select_low(const unsigned* __restrict__ hist,
                                           unsigned rank, unsigned hi_bits,
                                           unsigned* chunk, float* out_val) {
    int tid = threadIdx.x;
    unsigned s = 0;
    for (int k = 0; k < 64; k++) s += hist[tid * 64 + k];
    chunk[tid] = s;
    __syncthreads();
    if (tid == 0) {
        unsigned run = 0;
        for (int i = 0; i < 1024; i++) { unsigned c = chunk[i]; chunk[i] = run; run += c; }
    }
    __syncthreads();
    unsigned c = chunk[tid];
    for (int k = 0; k < 64; k++) {
        unsigned h = hist[tid * 64 + k];
        if (rank >= c && rank < c + h)
            *out_val = __uint_as_float((hi_bits << 16) | (unsigned)(tid * 64 + k));
        c += h;
    }
    __syncthreads();
}

__global__ void k_sel2(const float* __restrict__ HtRM) {
    __shared__ unsigned chunk[1024];
    __shared__ float vsh[2];
    select_low(g_hist2a, RANK0 - g_cumA, g_bA, chunk, &vsh[0]);
    select_low(g_hist2b, RANK1 - g_cumB, g_bB, chunk, &vsh[1]);
    if (threadIdx.x == 0) {
        double pos = 0.99 * (double)(TOTAL - 1);
        double fr  = pos - floor(pos);
        double q = (double)vsh[0] + fr * ((double)vsh[1] - (double)vsh[0]);
        g_scale = HtRM[0] / (float)q;
    }
}

// ---------------------------------------------------------------------------
__global__ void k_final(const float* __restrict__ Wt, float* __restrict__ out) {
    __shared__ float sw[12];
    if (threadIdx.x < 12) sw[threadIdx.x] = Wt[threadIdx.x];
    __syncthreads();
    float wt[12];
#pragma unroll
    for (int t = 0; t < 12; t++) wt[t] = sw[t];
    float sc = g_scale;
    const int NG = N_PIX / 4;
    float4* out4 = (float4*)out;
    int i = blockIdx.x * blockDim.x + threadIdx.x;
    int stride = gridDim.x * blockDim.x;
    for (int g = i; g < NG; g += stride) {
        float4 cc[4];
#pragma unroll
        for (int q = 0; q < 4; q++) {
            float4 c4 = g_Wc[4 * g + q];
            cc[q] = make_float4(c4.x * sc, c4.y * sc, c4.z * sc, c4.w * sc);
        }
#pragma unroll
        for (int c = 0; c < 3; c++) {
            float4 o;
            float* op = &o.x;
#pragma unroll
            for (int q = 0; q < 4; q++) {
                float t = wt[c*4+0]*cc[q].x + wt[c*4+1]*cc[q].y
                        + wt[c*4+2]*cc[q].z + wt[c*4+3]*cc[q].w;
                float e = __expf(-t);
                op[q] = fminf(fmaxf(e, 0.0f), 1.0f);
            }
            out4[c * NG + g] = o;
        }
    }
}

// ---------------------------------------------------------------------------
extern "C" void kernel_launch(void* const* d_in, const int* in_sizes, int n_in,
                              void* d_out, int out_size) {
    const float* pic = (const float*)d_in[0];
    const float* Wt  = (const float*)d_in[1];
    const float* Ht  = (const float*)d_in[2];
    const float* W0  = (const float*)d_in[3];
    const float* H0  = (const float*)d_in[4];
    float* out = (float*)d_out;

    static int smem_set = 0;
    if (!smem_set) {
        cudaFuncSetAttribute(k_loop, cudaFuncAttributeMaxDynamicSharedMemorySize,
                             SMEM_BYTES);
        smem_set = 1;
    }

    k_init_a<<<592, 256>>>();                          // launch 1
    k_init_b<<<128, 256>>>();                          // launch 2
    k_init_c<<<1, 32>>>();                             // launch 3
    k_loop<<<GRID, NTHR, SMEM_BYTES>>>(pic, W0, H0);   // launch 4 <- ncu slot
    k_hsum<<<256, 256>>>();
    k_sel1<<<1, 1024>>>();
    k_hist2<<<592, 256>>>();
    k_sel2<<<1, 1024>>>(Ht);
    k_final<<<592, 256>>>(Wt, out);
}